// round 6
// baseline (speedup 1.0000x reference)
#include <cuda_runtime.h>
#include <cuda_bf16.h>
#include <cstdint>

#define FULL 0xffffffffu

// Order-preserving float->uint map (2 SASS ops)
__device__ __forceinline__ unsigned f2o(float f) {
    unsigned b = __float_as_uint(f);
    return b ^ ((unsigned)((int)b >> 31) | 0x80000000u);
}
// inverse map
__device__ __forceinline__ float o2f(unsigned x) {
    unsigned b = x ^ ((unsigned)((int)(~x) >> 31) | 0x80000000u);
    return __uint_as_float(b);
}

// descending compare-exchange on (key,id)
#define CSWAP(A, B)                                     \
    {                                                   \
        bool p = k[A] < k[B];                           \
        unsigned tk = p ? k[B] : k[A];                  \
        k[B] = p ? k[A] : k[B];                         \
        k[A] = tk;                                      \
        int ti = p ? id[B] : id[A];                     \
        id[B] = p ? id[A] : id[B];                      \
        id[A] = ti;                                     \
    }

// Two tokens per warp: half = lane>>4, q = lane&15.
// Lane q owns experts [q*16, q*16+16). Group (32 experts) = lane pair (2g, 2g+1).
__global__ void __launch_bounds__(256, 6)
noaux_router_kernel(const float* __restrict__ logits,
                    const float* __restrict__ bias,
                    float* __restrict__ out,
                    int T, int write_ids)
{
    __shared__ float sbias[16 * 20];        // padded: row r at [r*20 .. r*20+15]
    __shared__ uint2 pq[256 * 7 + 4];       // per-thread sorted tail, slots 1..7
    {
        const int t = threadIdx.x;
        sbias[(t >> 4) * 20 + (t & 15)] = bias[t];
    }
    __syncthreads();

    const int warpid = blockIdx.x * (blockDim.x >> 5) + (threadIdx.x >> 5);
    if (warpid * 2 >= T) return;
    const int lane = threadIdx.x & 31;
    const int half = lane >> 4;
    const int q    = lane & 15;
    const int tok  = warpid * 2 + half;
    const unsigned hm = 0xFFFFu << (half << 4);   // this token's 16-lane mask

    // ---- load 16 logits (4x LDG.128, batched for MLP) ----
    const float4* lp = reinterpret_cast<const float4*>(logits + (size_t)tok * 256 + q * 16);
    float4 xv4[4];
    #pragma unroll
    for (int i = 0; i < 4; i++) xv4[i] = lp[i];

    // ---- corrected scores (bias via conflict-free LDS.128) ----
    float mk[16];
    #pragma unroll
    for (int c = 0; c < 4; c++) {
        const float4 bv = *reinterpret_cast<const float4*>(&sbias[q * 20 + c * 4]);
        const float* xp = reinterpret_cast<const float*>(&xv4[c]);
        const float* bp = reinterpret_cast<const float*>(&bv);
        #pragma unroll
        for (int i = 0; i < 4; i++) {
            float e = __expf(-xp[i]);
            mk[c * 4 + i] = 1.0f / (1.0f + e) + bp[i];
        }
    }

    // ---- in-lane top-2 of 16 ----
    float m1 = -INFINITY, m2 = -INFINITY;
    #pragma unroll
    for (int i = 0; i < 16; i++) {
        float v   = mk[i];
        float nm2 = fmaxf(m2, fminf(m1, v));
        m1 = fmaxf(m1, v);
        m2 = nm2;
    }
    // merge with group partner (lane^1 stays inside the half)
    {
        float o1 = __shfl_xor_sync(FULL, m1, 1);
        float o2 = __shfl_xor_sync(FULL, m2, 1);
        float nm2 = fmaxf(fminf(m1, o1), fmaxf(m2, o2));
        m1 = fmaxf(m1, o1);
        m2 = nm2;
    }
    const float gscore = m1 + m2;                 // uniform across the pair
    const int   myg    = q >> 1;

    // ---- top-4 of 8 groups (tie-break: lowest group index) ----
    int cnt = 0;
    #pragma unroll
    for (int g = 0; g < 8; g++) {
        float gsg = __shfl_sync(FULL, gscore, (half << 4) + 2 * g);
        cnt += (gsg > gscore) || (gsg == gscore && g < myg);
    }
    const bool sel = (cnt < 4);

    // ---- keys ----
    unsigned ik[16];
    #pragma unroll
    for (int i = 0; i < 16; i++) ik[i] = f2o(mk[i]);

    // ---- redistribution: 8 live lanes x 16 -> 16 lanes x 8 ----
    const unsigned ball = __ballot_sync(FULL, sel);
    const unsigned hb   = (ball >> (half << 4)) & 0xFFFFu;    // live lanes in half
    const unsigned dmask = ~hb & 0xFFFFu;

    int n = __popc(dmask & ((1u << q) - 1u));     // my rank among dead lanes
    unsigned mm = hb; int off = 0, c;             // n-th set bit of hb
    c = __popc(mm & 0xFFu); if (n >= c) { n -= c; off = 8;  mm >>= 8; }
    c = __popc(mm & 0xFu);  if (n >= c) { n -= c; off += 4; mm >>= 4; }
    c = __popc(mm & 0x3u);  if (n >= c) { n -= c; off += 2; mm >>= 2; }
    c = (int)(mm & 1u);     if (n >= c) { off += 1; }
    const int src_q = off;
    const int srclane = (half << 4) + (sel ? q : src_q);

    unsigned k[8];
    int id[8];
    const int ibase = (sel ? (q << 4) : ((src_q << 4) + 8));
    #pragma unroll
    for (int j = 0; j < 8; j++) {
        unsigned up = __shfl_sync(FULL, ik[8 + j], srclane);
        k[j]  = sel ? ik[j] : up;
        id[j] = ibase + j;
    }

    // ---- sort 8 descending (optimal 19-comparator network, stable) ----
    CSWAP(0,1) CSWAP(2,3) CSWAP(4,5) CSWAP(6,7)
    CSWAP(0,2) CSWAP(1,3) CSWAP(4,6) CSWAP(5,7)
    CSWAP(1,2) CSWAP(5,6) CSWAP(0,4) CSWAP(3,7)
    CSWAP(1,5) CSWAP(2,6)
    CSWAP(1,4) CSWAP(3,6)
    CSWAP(2,4) CSWAP(3,5)
    CSWAP(3,4)

    // head in registers; tail (slots 1..7) spilled to smem
    uint2* myq = &pq[threadIdx.x * 7];
    #pragma unroll
    for (int j = 1; j < 8; j++)
        myq[j - 1] = make_uint2(k[j], (unsigned)id[j]);

    unsigned khead = k[0];
    unsigned hid   = (unsigned)id[0];

    // ---- global top-8 per half: 8 rounds, both tokens in lockstep ----
    unsigned myid = 0, mkey = 0;
    const uint2* pp = myq;
    #pragma unroll
    for (int r = 0; r < 8; r++) {
        uint2 nxt = *pp;                           // prefetch next head (off critical path)
        unsigned m   = __reduce_max_sync(hm, khead);
        unsigned cnd = (khead == m) ? hid : 0x1FFu;
        unsigned wid = __reduce_min_sync(hm, cnd); // lowest expert id on ties
        bool win     = (cnd == wid);
        bool cap     = (q == r);
        myid = cap ? wid : myid;
        mkey = cap ? m   : mkey;
        pp    = win ? pp + 1 : pp;
        khead = win ? nxt.x : khead;
        hid   = win ? nxt.y : hid;
    }

    // ---- epilogue: recover uncorrected sigmoid from winner key ----
    float sc = o2f(mkey);
    float b  = sbias[(((int)myid >> 4) * 20) + ((int)myid & 15)];
    float w  = sc - b;                             // (sig+bias)-bias ~= sig

    float wsum = w;                                // xor d<8 stays within octet
    #pragma unroll
    for (int d = 1; d < 8; d <<= 1)
        wsum += __shfl_xor_sync(FULL, wsum, d);

    if (q < 8) {
        const float scale = 2.5f / (wsum + 1e-20f);
        out[(size_t)tok * 8 + q] = w * scale;
        if (write_ids)
            out[(size_t)T * 8 + (size_t)tok * 8 + q] = (float)myid;
    }
}

extern "C" void kernel_launch(void* const* d_in, const int* in_sizes, int n_in,
                              void* d_out, int out_size)
{
    const float* logits = (const float*)d_in[0];
    const float* bias   = (const float*)d_in[1];
    const int E = in_sizes[1];            // 256
    const int T = in_sizes[0] / E;        // 131072
    float* out = (float*)d_out;

    const int write_ids = (out_size >= T * 16) ? 1 : 0;

    const int warps = (T + 1) / 2;        // 2 tokens per warp
    const int warps_per_block = 8;        // 256 threads
    const int blocks = (warps + warps_per_block - 1) / warps_per_block;
    noaux_router_kernel<<<blocks, 256>>>(logits, bias, out, T, write_ids);
}

// round 7
// speedup vs baseline: 1.0328x; 1.0328x over previous
#include <cuda_runtime.h>
#include <cuda_bf16.h>
#include <cstdint>

#define FULL 0xffffffffu

// Order-preserving float->uint map (2 SASS ops)
__device__ __forceinline__ unsigned f2o(float f) {
    unsigned b = __float_as_uint(f);
    return b ^ ((unsigned)((int)b >> 31) | 0x80000000u);
}
// inverse map (bijective)
__device__ __forceinline__ float o2f(unsigned x) {
    unsigned b = x ^ ((unsigned)((int)(~x) >> 31) | 0x80000000u);
    return __uint_as_float(b);
}
__device__ __forceinline__ unsigned umax2(unsigned a, unsigned b) { return a > b ? a : b; }
__device__ __forceinline__ unsigned umin2(unsigned a, unsigned b) { return a < b ? a : b; }

// descending compare-exchange on (key,id)
#define CSWAP(A, B)                                     \
    {                                                   \
        bool p = k[A] < k[B];                           \
        unsigned tk = p ? k[B] : k[A];                  \
        k[B] = p ? k[A] : k[B];                         \
        k[A] = tk;                                      \
        int ti = p ? id[B] : id[A];                     \
        id[B] = p ? id[A] : id[B];                      \
        id[A] = ti;                                     \
    }

// Two tokens per warp: half = lane>>4, q = lane&15.
// Lane q owns experts [q*16, q*16+16). Group (32 experts) = lane pair (2g, 2g+1).
__global__ void __launch_bounds__(256, 7)
noaux_router_kernel(const float* __restrict__ logits,
                    const float* __restrict__ bias,
                    float* __restrict__ out,
                    int T, int write_ids)
{
    __shared__ float sbias[16 * 20];        // padded: row r at [r*20 .. r*20+15]
    __shared__ uint2 pq[256 * 7 + 4];       // per-thread sorted tail, slots 1..7
    {
        const int t = threadIdx.x;
        sbias[(t >> 4) * 20 + (t & 15)] = bias[t];
    }
    __syncthreads();

    const int warpid = blockIdx.x * (blockDim.x >> 5) + (threadIdx.x >> 5);
    if (warpid * 2 >= T) return;
    const int lane = threadIdx.x & 31;
    const int half = lane >> 4;
    const int q    = lane & 15;
    const int tok  = warpid * 2 + half;
    const unsigned hm = 0xFFFFu << (half << 4);   // this token's 16-lane mask

    // ---- load 16 logits (4x LDG.128, batched for MLP) ----
    const float4* lp = reinterpret_cast<const float4*>(logits + (size_t)tok * 256 + q * 16);
    float4 xv4[4];
    #pragma unroll
    for (int i = 0; i < 4; i++) xv4[i] = lp[i];

    // ---- corrected scores -> integer keys directly (no float array kept) ----
    // in-lane top-2 tracked in key domain (order-preserving)
    unsigned ik[16];
    unsigned m1 = 0, m2 = 0;                      // keys are >0 for finite scores
    #pragma unroll
    for (int c = 0; c < 4; c++) {
        const float4 bv = *reinterpret_cast<const float4*>(&sbias[q * 20 + c * 4]);
        const float* xp = reinterpret_cast<const float*>(&xv4[c]);
        const float* bp = reinterpret_cast<const float*>(&bv);
        #pragma unroll
        for (int i = 0; i < 4; i++) {
            float e = __expf(-xp[i]);
            float s = 1.0f / (1.0f + e) + bp[i];
            unsigned kk = f2o(s);
            ik[c * 4 + i] = kk;
            m2 = umax2(m2, umin2(m1, kk));
            m1 = umax2(m1, kk);
        }
    }
    // merge with group partner (lane^1 stays inside the half)
    {
        unsigned o1 = __shfl_xor_sync(FULL, m1, 1);
        unsigned o2 = __shfl_xor_sync(FULL, m2, 1);
        unsigned nm2 = umax2(umin2(m1, o1), umax2(m2, o2));
        m1 = umax2(m1, o1);
        m2 = nm2;
    }
    // exact float group score (bijective recovery -> bit-identical to reference)
    const float gscore = o2f(m1) + o2f(m2);
    const int   myg    = q >> 1;

    // ---- top-4 of 8 groups (tie-break: lowest group index) ----
    int cnt = 0;
    #pragma unroll
    for (int g = 0; g < 8; g++) {
        float gsg = __shfl_sync(FULL, gscore, (half << 4) + 2 * g);
        cnt += (gsg > gscore) || (gsg == gscore && g < myg);
    }
    const bool sel = (cnt < 4);

    // ---- redistribution: 8 live lanes x 16 -> 16 lanes x 8 ----
    const unsigned ball = __ballot_sync(FULL, sel);
    const unsigned hb   = (ball >> (half << 4)) & 0xFFFFu;    // live lanes in half
    const unsigned dmask = ~hb & 0xFFFFu;

    int n = __popc(dmask & ((1u << q) - 1u));     // my rank among dead lanes
    unsigned mm = hb; int off = 0, c;             // n-th set bit of hb
    c = __popc(mm & 0xFFu); if (n >= c) { n -= c; off = 8;  mm >>= 8; }
    c = __popc(mm & 0xFu);  if (n >= c) { n -= c; off += 4; mm >>= 4; }
    c = __popc(mm & 0x3u);  if (n >= c) { n -= c; off += 2; mm >>= 2; }
    c = (int)(mm & 1u);     if (n >= c) { off += 1; }
    const int src_q = off;
    const int srclane = (half << 4) + (sel ? q : src_q);

    unsigned k[8];
    int id[8];
    const int ibase = (sel ? (q << 4) : ((src_q << 4) + 8));
    #pragma unroll
    for (int j = 0; j < 8; j++) {
        unsigned up = __shfl_sync(FULL, ik[8 + j], srclane);
        k[j]  = sel ? ik[j] : up;
        id[j] = ibase + j;
    }

    // ---- sort 8 descending (optimal 19-comparator network, stable) ----
    CSWAP(0,1) CSWAP(2,3) CSWAP(4,5) CSWAP(6,7)
    CSWAP(0,2) CSWAP(1,3) CSWAP(4,6) CSWAP(5,7)
    CSWAP(1,2) CSWAP(5,6) CSWAP(0,4) CSWAP(3,7)
    CSWAP(1,5) CSWAP(2,6)
    CSWAP(1,4) CSWAP(3,6)
    CSWAP(2,4) CSWAP(3,5)
    CSWAP(3,4)

    // head in registers; tail (slots 1..7) spilled to smem
    uint2* myq = &pq[threadIdx.x * 7];
    #pragma unroll
    for (int j = 1; j < 8; j++)
        myq[j - 1] = make_uint2(k[j], (unsigned)id[j]);

    unsigned khead = k[0];
    unsigned hid   = (unsigned)id[0];

    // ---- global top-8 per half: 8 rounds, both tokens in lockstep ----
    unsigned myid = 0, mkey = 0;
    const uint2* pp = myq;
    #pragma unroll
    for (int r = 0; r < 8; r++) {
        uint2 nxt = *pp;                           // prefetch next head (off critical path)
        unsigned m   = __reduce_max_sync(hm, khead);
        unsigned cnd = (khead == m) ? hid : 0x1FFu;
        unsigned wid = __reduce_min_sync(hm, cnd); // lowest expert id on ties
        bool win     = (cnd == wid);
        bool cap     = (q == r);
        myid = cap ? wid : myid;
        mkey = cap ? m   : mkey;
        pp    = win ? pp + 1 : pp;
        khead = win ? nxt.x : khead;
        hid   = win ? nxt.y : hid;
    }

    // ---- epilogue: recover uncorrected sigmoid from winner key ----
    float sc = o2f(mkey);
    float b  = sbias[(((int)myid >> 4) * 20) + ((int)myid & 15)];
    float w  = sc - b;                             // (sig+bias)-bias ~= sig

    float wsum = w;                                // xor d<8 stays within octet
    #pragma unroll
    for (int d = 1; d < 8; d <<= 1)
        wsum += __shfl_xor_sync(FULL, wsum, d);

    if (q < 8) {
        const float scale = 2.5f / (wsum + 1e-20f);
        out[(size_t)tok * 8 + q] = w * scale;
        if (write_ids)
            out[(size_t)T * 8 + (size_t)tok * 8 + q] = (float)myid;
    }
}

extern "C" void kernel_launch(void* const* d_in, const int* in_sizes, int n_in,
                              void* d_out, int out_size)
{
    const float* logits = (const float*)d_in[0];
    const float* bias   = (const float*)d_in[1];
    const int E = in_sizes[1];            // 256
    const int T = in_sizes[0] / E;        // 131072
    float* out = (float*)d_out;

    const int write_ids = (out_size >= T * 16) ? 1 : 0;

    const int warps = (T + 1) / 2;        // 2 tokens per warp
    const int warps_per_block = 8;        // 256 threads
    const int blocks = (warps + warps_per_block - 1) / warps_per_block;
    noaux_router_kernel<<<blocks, 256>>>(logits, bias, out, T, write_ids);
}

// round 8
// speedup vs baseline: 1.0644x; 1.0306x over previous
#include <cuda_runtime.h>
#include <cuda_bf16.h>
#include <cstdint>

#define FULL 0xffffffffu

// Order-preserving float->uint map (2 SASS ops)
__device__ __forceinline__ unsigned f2o(float f) {
    unsigned b = __float_as_uint(f);
    return b ^ ((unsigned)((int)b >> 31) | 0x80000000u);
}
// inverse map (bijective)
__device__ __forceinline__ float o2f(unsigned x) {
    unsigned b = x ^ ((unsigned)((int)(~x) >> 31) | 0x80000000u);
    return __uint_as_float(b);
}

// descending compare-exchange on (key,id)
#define CSWAP(A, B)                                     \
    {                                                   \
        bool p = k[A] < k[B];                           \
        unsigned tk = p ? k[B] : k[A];                  \
        k[B] = p ? k[A] : k[B];                         \
        k[A] = tk;                                      \
        int ti = p ? id[B] : id[A];                     \
        id[B] = p ? id[A] : id[B];                      \
        id[A] = ti;                                     \
    }

// Two tokens per warp: half = lane>>4, q = lane&15.
// Lane q owns experts [q*16, q*16+16). Group (32 experts) = lane pair (2g, 2g+1).
__global__ void __launch_bounds__(256, 8)
noaux_router_kernel(const float* __restrict__ logits,
                    const float* __restrict__ bias,
                    float* __restrict__ out,
                    int T, int write_ids)
{
    __shared__ float sbias[16 * 20];          // padded: row r at [r*20 .. r*20+15]
    __shared__ unsigned pk[8 * 256];          // tail keys, interleaved [slot*256+tid]
    {                                         // slot 7 = pad (never a real candidate)
        const int t = threadIdx.x;
        sbias[(t >> 4) * 20 + (t & 15)] = bias[t];
    }
    __syncthreads();

    const int warpid = blockIdx.x * (blockDim.x >> 5) + (threadIdx.x >> 5);
    if (warpid * 2 >= T) return;
    const int lane = threadIdx.x & 31;
    const int half = lane >> 4;
    const int q    = lane & 15;
    const int tok  = warpid * 2 + half;
    const unsigned hm = 0xFFFFu << (half << 4);   // this token's 16-lane mask

    // ---- load 16 logits (4x LDG.128, batched for MLP) ----
    const float4* lp = reinterpret_cast<const float4*>(logits + (size_t)tok * 256 + q * 16);
    float4 xv4[4];
    #pragma unroll
    for (int i = 0; i < 4; i++) xv4[i] = lp[i];

    // ---- corrected scores (float domain; f2o deferred) + in-lane top-2 ----
    float mk[16];
    float m1 = -INFINITY, m2 = -INFINITY;
    #pragma unroll
    for (int c = 0; c < 4; c++) {
        const float4 bv = *reinterpret_cast<const float4*>(&sbias[q * 20 + c * 4]);
        const float* xp = reinterpret_cast<const float*>(&xv4[c]);
        const float* bp = reinterpret_cast<const float*>(&bv);
        #pragma unroll
        for (int i = 0; i < 4; i++) {
            float e = __expf(-xp[i]);
            float s = 1.0f / (1.0f + e) + bp[i];
            mk[c * 4 + i] = s;
            m2 = fmaxf(m2, fminf(m1, s));
            m1 = fmaxf(m1, s);
        }
    }
    // merge with group partner (lane^1 stays inside the half)
    {
        float o1 = __shfl_xor_sync(FULL, m1, 1);
        float o2 = __shfl_xor_sync(FULL, m2, 1);
        float nm2 = fmaxf(fminf(m1, o1), fmaxf(m2, o2));
        m1 = fmaxf(m1, o1);
        m2 = nm2;
    }
    const float gscore = m1 + m2;                 // uniform across the pair
    const int   myg    = q >> 1;

    // ---- top-4 of 8 groups (tie-break: lowest group index) ----
    int cnt = 0;
    #pragma unroll
    for (int g = 0; g < 8; g++) {
        float gsg = __shfl_sync(FULL, gscore, (half << 4) + 2 * g);
        cnt += (gsg > gscore) || (gsg == gscore && g < myg);
    }
    const bool sel = (cnt < 4);

    // ---- redistribution: 8 live lanes x 16 -> 16 lanes x 8 ----
    const unsigned ball = __ballot_sync(FULL, sel);
    const unsigned hb   = (ball >> (half << 4)) & 0xFFFFu;    // live lanes in half
    const unsigned dmask = ~hb & 0xFFFFu;

    int n = __popc(dmask & ((1u << q) - 1u));     // my rank among dead lanes
    unsigned mm = hb; int off = 0, c;             // n-th set bit of hb
    c = __popc(mm & 0xFFu); if (n >= c) { n -= c; off = 8;  mm >>= 8; }
    c = __popc(mm & 0xFu);  if (n >= c) { n -= c; off += 4; mm >>= 4; }
    c = __popc(mm & 0x3u);  if (n >= c) { n -= c; off += 2; mm >>= 2; }
    c = (int)(mm & 1u);     if (n >= c) { off += 1; }
    const int src_q = off;
    const int srclane = (half << 4) + (sel ? q : src_q);

    unsigned k[8];
    int id[8];
    const int ibase = (sel ? (q << 4) : ((src_q << 4) + 8));
    #pragma unroll
    for (int j = 0; j < 8; j++) {
        float up = __shfl_sync(FULL, mk[8 + j], srclane);
        k[j]  = f2o(sel ? mk[j] : up);
        id[j] = ibase + j;
    }

    // ---- sort 8 descending (optimal 19-comparator network, stable) ----
    CSWAP(0,1) CSWAP(2,3) CSWAP(4,5) CSWAP(6,7)
    CSWAP(0,2) CSWAP(1,3) CSWAP(4,6) CSWAP(5,7)
    CSWAP(1,2) CSWAP(5,6) CSWAP(0,4) CSWAP(3,7)
    CSWAP(1,5) CSWAP(2,6)
    CSWAP(1,4) CSWAP(3,6)
    CSWAP(2,4) CSWAP(3,5)
    CSWAP(3,4)

    // tail keys -> conflict-free interleaved smem; tail ids -> packed bytes
    #pragma unroll
    for (int j = 1; j < 8; j++)
        pk[(j - 1) * 256 + threadIdx.x] = k[j];

    unsigned khead = k[0];
    unsigned hid   = (unsigned)id[0];
    unsigned idlo  = (unsigned)id[1] | ((unsigned)id[2] << 8) |
                     ((unsigned)id[3] << 16) | ((unsigned)id[4] << 24);
    unsigned idhi  = (unsigned)id[5] | ((unsigned)id[6] << 8) |
                     ((unsigned)id[7] << 16);

    // ---- global top-8 per half: 8 rounds, both tokens in lockstep ----
    unsigned myid = 0, mkey = 0;
    int slot = 0;                                  // next tail slot to pop
    #pragma unroll
    for (int r = 0; r < 8; r++) {
        unsigned nk  = pk[slot * 256 + threadIdx.x];   // prefetch, conflict-free
        unsigned m   = __reduce_max_sync(hm, khead);
        unsigned cnd = (khead == m) ? hid : 0x1FFu;
        unsigned wid = __reduce_min_sync(hm, cnd);     // lowest expert id on ties
        bool win     = (cnd == wid);
        bool cap     = (q == r);
        myid = cap ? wid : myid;
        mkey = cap ? m   : mkey;
        unsigned nhid = idlo & 0xFFu;
        unsigned nlo  = __funnelshift_r(idlo, idhi, 8);
        slot  = win ? slot + 1 : slot;
        khead = win ? nk   : khead;
        hid   = win ? nhid : hid;
        idlo  = win ? nlo  : idlo;
        idhi  = win ? (idhi >> 8) : idhi;
    }

    // ---- epilogue: recover uncorrected sigmoid from winner key ----
    float sc = o2f(mkey);
    float b  = sbias[(((int)myid >> 4) * 20) + ((int)myid & 15)];
    float w  = sc - b;                             // (sig+bias)-bias ~= sig

    float wsum = w;                                // xor d<8 stays within octet
    #pragma unroll
    for (int d = 1; d < 8; d <<= 1)
        wsum += __shfl_xor_sync(FULL, wsum, d);

    if (q < 8) {
        const float scale = 2.5f / (wsum + 1e-20f);
        out[(size_t)tok * 8 + q] = w * scale;
        if (write_ids)
            out[(size_t)T * 8 + (size_t)tok * 8 + q] = (float)myid;
    }
}

extern "C" void kernel_launch(void* const* d_in, const int* in_sizes, int n_in,
                              void* d_out, int out_size)
{
    const float* logits = (const float*)d_in[0];
    const float* bias   = (const float*)d_in[1];
    const int E = in_sizes[1];            // 256
    const int T = in_sizes[0] / E;        // 131072
    float* out = (float*)d_out;

    const int write_ids = (out_size >= T * 16) ? 1 : 0;

    const int warps = (T + 1) / 2;        // 2 tokens per warp
    const int warps_per_block = 8;        // 256 threads
    const int blocks = (warps + warps_per_block - 1) / warps_per_block;
    noaux_router_kernel<<<blocks, 256>>>(logits, bias, out, T, write_ids);
}

// round 9
// speedup vs baseline: 1.2100x; 1.1368x over previous
#include <cuda_runtime.h>
#include <cuda_bf16.h>
#include <cstdint>

#define FULL 0xffffffffu

// Order-preserving float->uint map (2 SASS ops)
__device__ __forceinline__ unsigned f2o(float f) {
    unsigned b = __float_as_uint(f);
    return b ^ ((unsigned)((int)b >> 31) | 0x80000000u);
}
// inverse map (bijective)
__device__ __forceinline__ float o2f(unsigned x) {
    unsigned b = x ^ ((unsigned)((int)(~x) >> 31) | 0x80000000u);
    return __uint_as_float(b);
}
// 1-MUFU reciprocal (vs ~7-op IEEE division at default -prec-div)
__device__ __forceinline__ float frcp(float x) {
    float r;
    asm("rcp.approx.ftz.f32 %0, %1;" : "=f"(r) : "f"(x));
    return r;
}

// descending compare-exchange on (key,id)
#define CSWAP(A, B)                                     \
    {                                                   \
        bool p = k[A] < k[B];                           \
        unsigned tk = p ? k[B] : k[A];                  \
        k[B] = p ? k[A] : k[B];                         \
        k[A] = tk;                                      \
        int ti = p ? id[B] : id[A];                     \
        id[B] = p ? id[A] : id[B];                      \
        id[A] = ti;                                     \
    }

// Two tokens per warp: half = lane>>4, q = lane&15.
// Lane q owns experts [q*16, q*16+16). Group (32 experts) = lane pair (2g, 2g+1).
__global__ void __launch_bounds__(256, 8)
noaux_router_kernel(const float* __restrict__ logits,
                    const float* __restrict__ bias,
                    float* __restrict__ out,
                    int T, int write_ids)
{
    __shared__ float sbias[16 * 20];          // padded: row r at [r*20 .. r*20+15]
    __shared__ unsigned pk[8 * 256];          // tail keys, interleaved [slot*256+tid]
    {                                         // slot 7 = pad (never a real candidate)
        const int t = threadIdx.x;
        sbias[(t >> 4) * 20 + (t & 15)] = bias[t];
    }
    __syncthreads();

    const int warpid = blockIdx.x * (blockDim.x >> 5) + (threadIdx.x >> 5);
    if (warpid * 2 >= T) return;
    const int lane = threadIdx.x & 31;
    const int half = lane >> 4;
    const int q    = lane & 15;
    const int tok  = warpid * 2 + half;
    const unsigned hm = 0xFFFFu << (half << 4);   // this token's 16-lane mask

    // ---- load 16 logits (4x LDG.128, batched for MLP) ----
    const float4* lp = reinterpret_cast<const float4*>(logits + (size_t)tok * 256 + q * 16);
    float4 xv4[4];
    #pragma unroll
    for (int i = 0; i < 4; i++) xv4[i] = lp[i];

    // ---- corrected scores (fast sigmoid: EX2 + RCP.approx) + in-lane top-2 ----
    float mk[16];
    float m1 = -INFINITY, m2 = -INFINITY;
    #pragma unroll
    for (int c = 0; c < 4; c++) {
        const float4 bv = *reinterpret_cast<const float4*>(&sbias[q * 20 + c * 4]);
        const float* xp = reinterpret_cast<const float*>(&xv4[c]);
        const float* bp = reinterpret_cast<const float*>(&bv);
        #pragma unroll
        for (int i = 0; i < 4; i++) {
            float e = __expf(-xp[i]);
            float s = frcp(1.0f + e) + bp[i];
            mk[c * 4 + i] = s;
            m2 = fmaxf(m2, fminf(m1, s));
            m1 = fmaxf(m1, s);
        }
    }
    // merge with group partner (lane^1 stays inside the half)
    {
        float o1 = __shfl_xor_sync(FULL, m1, 1);
        float o2 = __shfl_xor_sync(FULL, m2, 1);
        float nm2 = fmaxf(fminf(m1, o1), fmaxf(m2, o2));
        m1 = fmaxf(m1, o1);
        m2 = nm2;
    }
    const float gscore = m1 + m2;                 // uniform across the pair
    const int   myg    = q >> 1;

    // ---- top-4 of 8 groups (tie-break: lowest group index) ----
    int cnt = 0;
    #pragma unroll
    for (int g = 0; g < 8; g++) {
        float gsg = __shfl_sync(FULL, gscore, (half << 4) + 2 * g);
        cnt += (gsg > gscore) || (gsg == gscore && g < myg);
    }
    const bool sel = (cnt < 4);

    // ---- redistribution: 8 live lanes x 16 -> 16 lanes x 8 ----
    const unsigned ball = __ballot_sync(FULL, sel);
    const unsigned hb   = (ball >> (half << 4)) & 0xFFFFu;    // live lanes in half
    const unsigned dmask = ~hb & 0xFFFFu;

    int n = __popc(dmask & ((1u << q) - 1u));     // my rank among dead lanes
    unsigned mm = hb; int off = 0, c;             // n-th set bit of hb
    c = __popc(mm & 0xFFu); if (n >= c) { n -= c; off = 8;  mm >>= 8; }
    c = __popc(mm & 0xFu);  if (n >= c) { n -= c; off += 4; mm >>= 4; }
    c = __popc(mm & 0x3u);  if (n >= c) { n -= c; off += 2; mm >>= 2; }
    c = (int)(mm & 1u);     if (n >= c) { off += 1; }
    const int src_q = off;
    const int srclane = (half << 4) + (sel ? q : src_q);

    unsigned k[8];
    int id[8];
    const int ibase = (sel ? (q << 4) : ((src_q << 4) + 8));
    #pragma unroll
    for (int j = 0; j < 8; j++) {
        float up = __shfl_sync(FULL, mk[8 + j], srclane);
        k[j]  = f2o(sel ? mk[j] : up);
        id[j] = ibase + j;
    }

    // ---- sort 8 descending (optimal 19-comparator network, stable) ----
    CSWAP(0,1) CSWAP(2,3) CSWAP(4,5) CSWAP(6,7)
    CSWAP(0,2) CSWAP(1,3) CSWAP(4,6) CSWAP(5,7)
    CSWAP(1,2) CSWAP(5,6) CSWAP(0,4) CSWAP(3,7)
    CSWAP(1,5) CSWAP(2,6)
    CSWAP(1,4) CSWAP(3,6)
    CSWAP(2,4) CSWAP(3,5)
    CSWAP(3,4)

    // tail keys -> conflict-free interleaved smem; tail ids -> packed bytes
    #pragma unroll
    for (int j = 1; j < 8; j++)
        pk[(j - 1) * 256 + threadIdx.x] = k[j];

    unsigned khead = k[0];
    unsigned hid   = (unsigned)id[0];
    unsigned idlo  = (unsigned)id[1] | ((unsigned)id[2] << 8) |
                     ((unsigned)id[3] << 16) | ((unsigned)id[4] << 24);
    unsigned idhi  = (unsigned)id[5] | ((unsigned)id[6] << 8) |
                     ((unsigned)id[7] << 16);

    // ---- global top-8 per half: 8 rounds, both tokens in lockstep ----
    unsigned myid = 0, mkey = 0;
    int slot = 0;                                  // next tail slot to pop
    #pragma unroll
    for (int r = 0; r < 8; r++) {
        unsigned nk  = pk[slot * 256 + threadIdx.x];   // prefetch, conflict-free
        unsigned m   = __reduce_max_sync(hm, khead);
        unsigned cnd = (khead == m) ? hid : 0x1FFu;
        unsigned wid = __reduce_min_sync(hm, cnd);     // lowest expert id on ties
        bool win     = (cnd == wid);
        bool cap     = (q == r);
        myid = cap ? wid : myid;
        mkey = cap ? m   : mkey;
        unsigned nhid = idlo & 0xFFu;
        unsigned nlo  = __funnelshift_r(idlo, idhi, 8);
        slot  = win ? slot + 1 : slot;
        khead = win ? nk   : khead;
        hid   = win ? nhid : hid;
        idlo  = win ? nlo  : idlo;
        idhi  = win ? (idhi >> 8) : idhi;
    }

    // ---- epilogue: recover uncorrected sigmoid from winner key ----
    float sc = o2f(mkey);
    float b  = sbias[(((int)myid >> 4) * 20) + ((int)myid & 15)];
    float w  = sc - b;                             // (sig+bias)-bias ~= sig

    float wsum = w;                                // xor d<8 stays within octet
    #pragma unroll
    for (int d = 1; d < 8; d <<= 1)
        wsum += __shfl_xor_sync(FULL, wsum, d);

    if (q < 8) {
        const float scale = 2.5f * frcp(wsum + 1e-20f);
        out[(size_t)tok * 8 + q] = w * scale;
        if (write_ids)
            out[(size_t)T * 8 + (size_t)tok * 8 + q] = (float)myid;
    }
}

extern "C" void kernel_launch(void* const* d_in, const int* in_sizes, int n_in,
                              void* d_out, int out_size)
{
    const float* logits = (const float*)d_in[0];
    const float* bias   = (const float*)d_in[1];
    const int E = in_sizes[1];            // 256
    const int T = in_sizes[0] / E;        // 131072
    float* out = (float*)d_out;

    const int write_ids = (out_size >= T * 16) ? 1 : 0;

    const int warps = (T + 1) / 2;        // 2 tokens per warp
    const int warps_per_block = 8;        // 256 threads
    const int blocks = (warps + warps_per_block - 1) / warps_per_block;
    noaux_router_kernel<<<blocks, 256>>>(logits, bias, out, T, write_ids);
}